// round 1
// baseline (speedup 1.0000x reference)
#include <cuda_runtime.h>
#include <math.h>

#define DIM    1024
#define PAR    8
#define NN     255          // nodes per tree
#define WIDTH  2040         // PAR * NN
#define DEPTH  7
#define NSTEP  (DEPTH + 1)  // 8 visited nodes per tree
#define NACT   (PAR * NSTEP) // 64 active nodes per row

// Static scratch for transposed W_out: [WIDTH][DIM] so each node's output
// contribution is a contiguous, coalescable 4KB row. (No dynamic allocation.)
__device__ float g_WoutT[WIDTH * DIM];

// ---------------------------------------------------------------------------
// Kernel 1: transpose W_out [DIM, WIDTH] -> g_WoutT [WIDTH, DIM]
// ---------------------------------------------------------------------------
__global__ __launch_bounds__(1024) void transpose_wout(const float* __restrict__ Wout) {
    __shared__ float tile[32][33];
    int wcol = blockIdx.x * 32 + threadIdx.x;  // width index (0..2039)
    int drow = blockIdx.y * 32 + threadIdx.y;  // dim index (0..1023)
    if (wcol < WIDTH) tile[threadIdx.y][threadIdx.x] = Wout[drow * WIDTH + wcol];
    __syncthreads();
    int od = blockIdx.y * 32 + threadIdx.x;    // dim (always < 1024)
    int ow = blockIdx.x * 32 + threadIdx.y;    // width
    if (ow < WIDTH) g_WoutT[ow * DIM + od] = tile[threadIdx.x][threadIdx.y];
}

// ---------------------------------------------------------------------------
// Kernel 2: fused FFF forward. One block per row (256 threads = 8 warps).
//   Stage 1: warp w traverses tree w: 8 dependent dots vs W_in rows.
//   Stage 2: all 256 threads accumulate 64 coalesced W_outT rows.
// ---------------------------------------------------------------------------
__global__ __launch_bounds__(256) void fff_kernel(
    const float* __restrict__ x,
    const float* __restrict__ Win,
    const float* __restrict__ bin,
    float* __restrict__ out)
{
    __shared__ float4 sx[DIM / 4];   // this row's input, 4KB
    __shared__ float  s_act[NACT];
    __shared__ int    s_widx[NACT];

    const int row  = blockIdx.x;
    const int tid  = threadIdx.x;
    const int warp = tid >> 5;
    const int lane = tid & 31;

    // Stage x row into smem: 256 threads x float4 = 1024 floats.
    sx[tid] = ((const float4*)(x + (size_t)row * DIM))[tid];
    __syncthreads();

    // ---- Stage 1: sequential tree descent, one warp per tree ----
    {
        int cur = 0;  // node index within this tree (0..254)
        #pragma unroll 1
        for (int step = 0; step < NSTEP; ++step) {
            const int wrow = warp * NN + cur;           // global width index
            const float4* __restrict__ Wr =
                (const float4*)(Win + (size_t)wrow * DIM);
            float sum = 0.f;
            #pragma unroll
            for (int k = 0; k < 8; ++k) {               // 32 floats / lane
                float4 wv = Wr[lane + 32 * k];
                float4 xv = sx[lane + 32 * k];
                sum += wv.x * xv.x + wv.y * xv.y + wv.z * xv.z + wv.w * xv.w;
            }
            #pragma unroll
            for (int off = 16; off; off >>= 1)          // butterfly: all lanes get sum
                sum += __shfl_xor_sync(0xffffffffu, sum, off);
            const float logit = sum + bin[wrow];
            if (lane == 0) {
                // silu(logit) = logit * sigmoid(logit)
                s_act[warp * NSTEP + step]  = logit / (1.f + expf(-logit));
                s_widx[warp * NSTEP + step] = wrow;
            }
            // current = 2*current + 1 + (logit > 0)  (platform algebra simplifies)
            cur = 2 * cur + 1 + (logit > 0.f ? 1 : 0);
        }
    }
    __syncthreads();

    // ---- Stage 2: out[row] = sum_i act_i * W_outT[widx_i, :] ----
    float4 acc = make_float4(0.f, 0.f, 0.f, 0.f);
    #pragma unroll 4
    for (int i = 0; i < NACT; ++i) {
        const float a = s_act[i];
        const float4 wv =
            ((const float4*)(g_WoutT + (size_t)s_widx[i] * DIM))[tid];
        acc.x += a * wv.x;
        acc.y += a * wv.y;
        acc.z += a * wv.z;
        acc.w += a * wv.w;
    }
    ((float4*)(out + (size_t)row * DIM))[tid] = acc;
}

// ---------------------------------------------------------------------------
extern "C" void kernel_launch(void* const* d_in, const int* in_sizes, int n_in,
                              void* d_out, int out_size) {
    const float* oldx  = (const float*)d_in[0];   // [4,2048,1024] f32
    const float* W_in  = (const float*)d_in[1];   // [2040,1024] f32
    const float* b_in  = (const float*)d_in[2];   // [2040] f32
    const float* W_out = (const float*)d_in[3];   // [1024,2040] f32
    float* out = (float*)d_out;

    const int B = in_sizes[0] / DIM;              // 8192 rows

    dim3 tgrid((WIDTH + 31) / 32, DIM / 32);
    transpose_wout<<<tgrid, dim3(32, 32)>>>(W_out);

    fff_kernel<<<B, 256>>>(oldx, W_in, b_in, out);
}

// round 3
// speedup vs baseline: 1.0157x; 1.0157x over previous
#include <cuda_runtime.h>
#include <math.h>

#define DIM    1024
#define PAR    8
#define NN     255          // nodes per tree
#define WIDTH  2040         // PAR * NN
#define DEPTH  7
#define NSTEP  (DEPTH + 1)  // 8 visited nodes per tree
#define NACT   (PAR * NSTEP) // 64 active nodes per row

// Static scratch for transposed W_out: [WIDTH][DIM] so each node's output
// contribution is a contiguous, coalescable 4KB row.
__device__ float g_WoutT[WIDTH * DIM];

// ---------------------------------------------------------------------------
// Kernel 1: transpose W_out [DIM, WIDTH] -> g_WoutT [WIDTH, DIM]
// ---------------------------------------------------------------------------
__global__ __launch_bounds__(1024) void transpose_wout(const float* __restrict__ Wout) {
    __shared__ float tile[32][33];
    int wcol = blockIdx.x * 32 + threadIdx.x;  // width index (0..2039)
    int drow = blockIdx.y * 32 + threadIdx.y;  // dim index (0..1023)
    if (wcol < WIDTH) tile[threadIdx.y][threadIdx.x] = Wout[drow * WIDTH + wcol];
    __syncthreads();
    int od = blockIdx.y * 32 + threadIdx.x;    // dim (always < 1024)
    int ow = blockIdx.x * 32 + threadIdx.y;    // width
    if (ow < WIDTH) g_WoutT[ow * DIM + od] = tile[threadIdx.x][threadIdx.y];
}

// ---------------------------------------------------------------------------
// Kernel 2: fused FFF forward. One block per row (256 threads = 8 warps).
//   Stage 1: warp w traverses tree w; x slice held in REGISTERS (no LDS
//            traffic on the L1 port — it was 1/3 of total port bytes).
//   Stage 2: all 256 threads accumulate 64 coalesced W_outT rows.
// ---------------------------------------------------------------------------
__global__ __launch_bounds__(256) void fff_kernel(
    const float* __restrict__ x,
    const float* __restrict__ Win,
    const float* __restrict__ bin,
    float* __restrict__ out)
{
    __shared__ float  s_act[NACT];
    __shared__ int    s_widx[NACT];

    const int row  = blockIdx.x;
    const int tid  = threadIdx.x;
    const int warp = tid >> 5;
    const int lane = tid & 31;

    // Each lane keeps its fixed slice of x in registers: elements
    // 4*(lane + 32k) .. +3, k = 0..7  (32 floats). Warps 1-7 L1-hit.
    const float4* __restrict__ xg = (const float4*)(x + (size_t)row * DIM);
    float4 xr[8];
    #pragma unroll
    for (int k = 0; k < 8; ++k) xr[k] = xg[lane + 32 * k];

    // ---- Stage 1: sequential tree descent, one warp per tree ----
    {
        int cur = 0;  // node index within this tree (0..254)
        #pragma unroll 1
        for (int step = 0; step < NSTEP; ++step) {
            const int wrow = warp * NN + cur;           // global width index
            const float4* __restrict__ Wr =
                (const float4*)(Win + (size_t)wrow * DIM);
            float sum = 0.f;
            #pragma unroll
            for (int k = 0; k < 8; ++k) {               // 32 floats / lane
                const float4 wv = Wr[lane + 32 * k];
                sum += wv.x * xr[k].x + wv.y * xr[k].y
                     + wv.z * xr[k].z + wv.w * xr[k].w;
            }
            #pragma unroll
            for (int off = 16; off; off >>= 1)          // butterfly: all lanes get sum
                sum += __shfl_xor_sync(0xffffffffu, sum, off);
            const float logit = sum + __ldg(bin + wrow);
            if (lane == 0) {
                // silu(logit) = logit * sigmoid(logit)
                s_act[warp * NSTEP + step]  = logit / (1.f + expf(-logit));
                s_widx[warp * NSTEP + step] = wrow;
            }
            cur = 2 * cur + 1 + (logit > 0.f ? 1 : 0);
        }
    }
    __syncthreads();

    // ---- Stage 2: out[row] = sum_i act_i * W_outT[widx_i, :] ----
    float4 acc = make_float4(0.f, 0.f, 0.f, 0.f);
    #pragma unroll 4
    for (int i = 0; i < NACT; ++i) {
        const float a = s_act[i];                        // LDS broadcast (1 wf)
        const float4 wv =
            ((const float4*)(g_WoutT + (size_t)s_widx[i] * DIM))[tid];
        acc.x += a * wv.x;
        acc.y += a * wv.y;
        acc.z += a * wv.z;
        acc.w += a * wv.w;
    }
    ((float4*)(out + (size_t)row * DIM))[tid] = acc;
}

// ---------------------------------------------------------------------------
extern "C" void kernel_launch(void* const* d_in, const int* in_sizes, int n_in,
                              void* d_out, int out_size) {
    const float* oldx  = (const float*)d_in[0];   // [4,2048,1024] f32
    const float* W_in  = (const float*)d_in[1];   // [2040,1024] f32
    const float* b_in  = (const float*)d_in[2];   // [2040] f32
    const float* W_out = (const float*)d_in[3];   // [1024,2040] f32
    float* out = (float*)d_out;

    const int B = in_sizes[0] / DIM;              // 8192 rows

    dim3 tgrid((WIDTH + 31) / 32, DIM / 32);
    transpose_wout<<<tgrid, dim3(32, 32)>>>(W_out);

    fff_kernel<<<B, 256>>>(oldx, W_in, b_in, out);
}